// round 9
// baseline (speedup 1.0000x reference)
#include <cuda_runtime.h>
#include <cuda_bf16.h>
#include <cstdint>

#define M_OUT 2049
#define MPAD  2112          // 33 * 64
#define NSIG  4096
#define KDIM  4096

static constexpr float CANG = (float)(-2.0 * 3.14 / 4096.0);
static constexpr float DEN  = (float)(4096.0 / 30.0);

// A planes: [pidx][row][k] bf16, pidx = part*3 + split, part 0=cos 1=sin
__device__ __align__(256) __nv_bfloat16 g_At[(size_t)6 * MPAD * KDIM];
// B planes: [p][n][k] bf16 (x transposed, demeaned, split)
__device__ __align__(256) __nv_bfloat16 g_Bt[(size_t)3 * NSIG * KDIM];
__device__ float g_mean[KDIM];
__device__ unsigned long long g_best[M_OUT];

// ---------------- helpers ----------------
__device__ __forceinline__ uint32_t smem_u32(const void* p) {
    uint32_t a;
    asm("{ .reg .u64 t; cvta.to.shared.u64 t, %1; cvt.u32.u64 %0, t; }" : "=r"(a) : "l"(p));
    return a;
}
__device__ __forceinline__ void cpa16(uint32_t s, const void* g) {
    asm volatile("cp.async.cg.shared.global [%0], [%1], 16;" :: "r"(s), "l"(g) : "memory");
}
__device__ __forceinline__ uint32_t lds32(uint32_t a) {
    uint32_t v;
    asm("ld.shared.b32 %0, [%1];" : "=r"(v) : "r"(a));
    return v;
}
__device__ __forceinline__ void mma_bf16(float* c, uint32_t a0, uint32_t a1,
                                         uint32_t a2, uint32_t a3,
                                         uint32_t b0, uint32_t b1) {
    asm volatile(
        "mma.sync.aligned.m16n8k16.row.col.f32.bf16.bf16.f32 "
        "{%0,%1,%2,%3}, {%4,%5,%6,%7}, {%8,%9}, {%0,%1,%2,%3};"
        : "+f"(c[0]), "+f"(c[1]), "+f"(c[2]), "+f"(c[3])
        : "r"(a0), "r"(a1), "r"(a2), "r"(a3), "r"(b0), "r"(b1));
}

// ---------------- kernel 1: per-row means ----------------
__global__ void mean_kernel(const float* __restrict__ x) {
    __shared__ float red[256];
    const int n = blockIdx.x;
    const float4* row = (const float4*)(x + (size_t)n * NSIG);
    float s = 0.f;
#pragma unroll
    for (int c = 0; c < 4; ++c) {
        float4 v = row[threadIdx.x + c * 256];
        s += (v.x + v.y) + (v.z + v.w);
    }
    red[threadIdx.x] = s;
    __syncthreads();
    for (int off = 128; off > 0; off >>= 1) {
        if (threadIdx.x < off) red[threadIdx.x] += red[threadIdx.x + off];
        __syncthreads();
    }
    if (threadIdx.x == 0) g_mean[n] = red[0] * (1.0f / 4096.0f);
}

// ---------------- kernel 2: trig table -> 6 bf16 split planes ----------------
__global__ void trig_kernel() {
    const long long idx = (long long)blockIdx.x * blockDim.x + threadIdx.x;
    if (idx >= (long long)MPAD * KDIM) return;
    const int i = (int)(idx >> 12);
    const int n = (int)(idx & 4095);
    float c = 0.f, s = 0.f;
    if (i < M_OUT) {
        const float t = (float)(i * n);
        const float a = CANG * t;
        const float kf = rintf(a * 0.63661977236758134f);
        const int   k  = (int)kf;
        float r = fmaf(kf, -1.57079601287841796875f, a);
        r       = fmaf(kf, -3.1391647326017916e-07f, r);
        r       = fmaf(kf, -5.3903025299577648e-15f, r);
        const float z = r * r;
        const float sinp = r * fmaf(z, fmaf(z, fmaf(z, -1.9515295891e-4f,
                                                8.3321608736e-3f),
                                        -1.6666654611e-1f), 1.0f);
        const float cosp = fmaf(z, fmaf(z, fmaf(z, fmaf(z, 2.443315711809948e-5f,
                                                    -1.388731625493765e-3f),
                                            4.166664568298827e-2f),
                                    -0.5f), 1.0f);
        const int q = k & 3;
        if (q == 0)      { c =  cosp; s =  sinp; }
        else if (q == 1) { c = -sinp; s =  cosp; }
        else if (q == 2) { c = -cosp; s = -sinp; }
        else             { c =  sinp; s = -cosp; }
    }
    float v = c;
#pragma unroll
    for (int part = 0; part < 2; ++part) {
        const __nv_bfloat16 b0 = __float2bfloat16_rn(v);
        const float r1 = v - __bfloat162float(b0);
        const __nv_bfloat16 b1 = __float2bfloat16_rn(r1);
        const float r2 = r1 - __bfloat162float(b1);
        const __nv_bfloat16 b2 = __float2bfloat16_rn(r2);
        const size_t base = ((size_t)(part * 3) * MPAD + i) * KDIM + n;
        g_At[base]                       = b0;
        g_At[base + (size_t)MPAD * KDIM] = b1;
        g_At[base + (size_t)2 * MPAD * KDIM] = b2;
        v = s;
    }
    if (idx < M_OUT) g_best[idx] = 0ull;
}

// ---------------- kernel 3: transpose + demean + split B ----------------
__global__ void bsplit_kernel(const float* __restrict__ x) {
    __shared__ float tile[32][33];
    const int k0 = blockIdx.x * 32;
    const int n0 = blockIdx.y * 32;
    const int tx = threadIdx.x, ty = threadIdx.y;   // 32 x 8
#pragma unroll
    for (int r = 0; r < 4; ++r) {
        const int k = ty + r * 8;
        tile[k][tx] = x[(size_t)(k0 + k) * NSIG + n0 + tx] - g_mean[k0 + k];
    }
    __syncthreads();
#pragma unroll
    for (int r = 0; r < 4; ++r) {
        const int n = ty + r * 8;
        const float v = tile[tx][n];
        const __nv_bfloat16 b0 = __float2bfloat16_rn(v);
        const float r1 = v - __bfloat162float(b0);
        const __nv_bfloat16 b1 = __float2bfloat16_rn(r1);
        const float r2 = r1 - __bfloat162float(b1);
        const __nv_bfloat16 b2 = __float2bfloat16_rn(r2);
        const size_t base = ((size_t)(n0 + n)) * KDIM + k0 + tx;
        g_Bt[base]                        = b0;
        g_Bt[base + (size_t)NSIG * KDIM]  = b1;
        g_Bt[base + (size_t)2 * NSIG * KDIM] = b2;
    }
}

// ---------------- kernel 4: bf16x6 HMMA dual GEMM + fused argmax ----------------
// smem per stage: A: 3 planes x 128 rows x 80B = 30720; B: 3 x 64 x 80B = 15360
#define SM_STAGE 46080
#define SM_APL   10240
#define SM_BOFF  30720
#define SM_BPL   5120
#define SM_TOTAL (2 * SM_STAGE)

__global__ __launch_bounds__(256, 2) void gemm_mma_kernel() {
    extern __shared__ char smem[];
    const uint32_t sb = smem_u32(smem);
    const int tid = threadIdx.x;
    const int warp = tid >> 5;
    const int lane = tid & 31;
    const int gr = lane >> 2;          // 0..7
    const int tig = lane & 3;          // 0..3
    const int wm = warp >> 1;          // 0..3 -> M' rows 32*wm
    const int wn = warp & 1;           // 0..1 -> N cols 32*wn
    const int i0 = blockIdx.y * 64;
    const int j0 = blockIdx.x * 64;

    // loader mapping (per thread): A 6 units, B 3 units
    const int lr  = tid >> 2;          // 0..63 row
    const int seg = tid & 3;           // 16B segment
    const __nv_bfloat16* gA[6];
    uint32_t sA[6];
#pragma unroll
    for (int p = 0; p < 6; ++p) {
        gA[p] = g_At + ((size_t)p * MPAD + i0 + lr) * KDIM + seg * 8;
        sA[p] = sb + (p % 3) * SM_APL + ((p / 3) * 64 + lr) * 80 + seg * 16;
    }
    const __nv_bfloat16* gB[3];
    uint32_t sB[3];
#pragma unroll
    for (int p = 0; p < 3; ++p) {
        gB[p] = g_Bt + ((size_t)p * NSIG + j0 + lr) * KDIM + seg * 8;
        sB[p] = sb + SM_BOFF + p * SM_BPL + lr * 80 + seg * 16;
    }

    float acc[2][4][4];
#pragma unroll
    for (int mt = 0; mt < 2; ++mt)
#pragma unroll
        for (int nt = 0; nt < 4; ++nt)
#pragma unroll
            for (int e = 0; e < 4; ++e) acc[mt][nt][e] = 0.f;

    // prologue: stage 0 = k-tile 0
    {
#pragma unroll
        for (int p = 0; p < 6; ++p) cpa16(sA[p], gA[p]);
#pragma unroll
        for (int p = 0; p < 3; ++p) cpa16(sB[p], gB[p]);
        asm volatile("cp.async.commit_group;" ::: "memory");
    }

    const uint32_t aW = sb + (32 * wm + gr) * 80 + tig * 4;
    const uint32_t bW = sb + SM_BOFF + (32 * wn + gr) * 80 + tig * 4;

    for (int kt = 0; kt < KDIM / 32; ++kt) {
        if (kt + 1 < KDIM / 32) {
            const int ke = (kt + 1) * 32;
            const uint32_t so = ((kt + 1) & 1) * SM_STAGE;
#pragma unroll
            for (int p = 0; p < 6; ++p) cpa16(sA[p] + so, gA[p] + ke);
#pragma unroll
            for (int p = 0; p < 3; ++p) cpa16(sB[p] + so, gB[p] + ke);
            asm volatile("cp.async.commit_group;" ::: "memory");
            asm volatile("cp.async.wait_group 1;" ::: "memory");
        } else {
            asm volatile("cp.async.wait_group 0;" ::: "memory");
        }
        __syncthreads();

        const uint32_t so = (kt & 1) * SM_STAGE;
#pragma unroll
        for (int ks = 0; ks < 2; ++ks) {
            const uint32_t kb = ks * 32;
            // B fragments: 3 planes x 4 n-tiles x 2 regs
            uint32_t bf[3][4][2];
#pragma unroll
            for (int q = 0; q < 3; ++q)
#pragma unroll
                for (int nt = 0; nt < 4; ++nt) {
                    const uint32_t a = bW + so + q * SM_BPL + nt * (8 * 80) + kb;
                    bf[q][nt][0] = lds32(a);
                    bf[q][nt][1] = lds32(a + 16);
                }
            // A planes with their B-plane partner lists:
            // p=0: q {0,1,2}; p=1: q {0,1}; p=2: q {0}
#pragma unroll
            for (int p = 0; p < 3; ++p) {
#pragma unroll
                for (int mt = 0; mt < 2; ++mt) {
                    const uint32_t a = aW + so + p * SM_APL + mt * (16 * 80) + kb;
                    const uint32_t a0 = lds32(a);
                    const uint32_t a1 = lds32(a + 8 * 80);
                    const uint32_t a2 = lds32(a + 16);
                    const uint32_t a3 = lds32(a + 8 * 80 + 16);
                    const int nq = (p == 0) ? 3 : (p == 1) ? 2 : 1;
#pragma unroll
                    for (int q = 0; q < 3; ++q) {
                        if (q < nq) {
#pragma unroll
                            for (int nt = 0; nt < 4; ++nt)
                                mma_bf16(acc[mt][nt], a0, a1, a2, a3,
                                         bf[q][nt][0], bf[q][nt][1]);
                        }
                    }
                }
            }
        }
        __syncthreads();
    }

    // ---- epilogue: stage-0 smem reused as D[128][66] f32 + sbest ----
    float* Dsm = (float*)smem;
    unsigned long long* sbest = (unsigned long long*)(smem + 128 * 66 * 4);
#pragma unroll
    for (int mt = 0; mt < 2; ++mt)
#pragma unroll
        for (int nt = 0; nt < 4; ++nt) {
            const int m = 32 * wm + 16 * mt;
            const int n = 32 * wn + 8 * nt + 2 * tig;
            *(float2*)(&Dsm[(m + gr) * 66 + n])     = make_float2(acc[mt][nt][0], acc[mt][nt][1]);
            *(float2*)(&Dsm[(m + gr + 8) * 66 + n]) = make_float2(acc[mt][nt][2], acc[mt][nt][3]);
        }
    if (tid < 64) sbest[tid] = 0ull;
    __syncthreads();

    {
        const int r = tid & 63;
        const int c0 = (tid >> 6) * 16;
        float best = -1.0f;
        unsigned bj = 0;
#pragma unroll
        for (int c = 0; c < 16; ++c) {
            const int col = c0 + c;
            const float re = Dsm[r * 66 + col];
            const float im = Dsm[(64 + r) * 66 + col];
            const float v = fmaf(re, re, im * im);
            const unsigned j = (unsigned)(j0 + col);
            if (v > best) { best = v; bj = j; }
        }
        const unsigned long long p =
            ((unsigned long long)__float_as_uint(best) << 32) |
            (unsigned long long)(0xFFFFFFFFu - bj);
        atomicMax(&sbest[r], p);
    }
    __syncthreads();
    if (tid < 64) {
        const int gi = i0 + tid;
        if (gi < M_OUT) atomicMax(&g_best[gi], sbest[tid]);
    }
}

// ---------------- kernel 5: map argmax index -> heart rate ----------------
__global__ void final_kernel(float* __restrict__ out) {
    const int i = blockIdx.x * blockDim.x + threadIdx.x;
    if (i < M_OUT) {
        const unsigned j = 0xFFFFFFFFu - (unsigned)(g_best[i] & 0xFFFFFFFFull);
        const float freq = (float)j / DEN;
        out[i] = freq * 60.0f;
    }
}

extern "C" void kernel_launch(void* const* d_in, const int* in_sizes, int n_in,
                              void* d_out, int out_size) {
    const float* x = (const float*)d_in[0];
    float* out = (float*)d_out;

    cudaFuncSetAttribute(gemm_mma_kernel,
                         cudaFuncAttributeMaxDynamicSharedMemorySize, SM_TOTAL);

    mean_kernel<<<KDIM, 256>>>(x);

    const long long trig_total = (long long)MPAD * KDIM;
    trig_kernel<<<(unsigned)((trig_total + 255) / 256), 256>>>();

    bsplit_kernel<<<dim3(KDIM / 32, NSIG / 32), dim3(32, 8)>>>(x);

    gemm_mma_kernel<<<dim3(NSIG / 64, MPAD / 64), 256, SM_TOTAL>>>();

    final_kernel<<<(M_OUT + 255) / 256, 256>>>(out);
}

// round 10
// speedup vs baseline: 2.6282x; 2.6282x over previous
#include <cuda_runtime.h>
#include <cuda_bf16.h>
#include <cstdint>

#define M_OUT 2049
#define MPAD  2112          // 33 * 64
#define NSIG  4096
#define KDIM  4096

static constexpr float CANG = (float)(-2.0 * 3.14 / 4096.0);
static constexpr float DEN  = (float)(4096.0 / 30.0);

// A planes: pidx = part*2 + split (part 0=cos 1=sin), [pidx][row][k] bf16
__device__ __align__(256) __nv_bfloat16 g_At[(size_t)4 * MPAD * KDIM];
// B planes: [split][n][k] bf16 (x transposed, demeaned, 2-way split)
__device__ __align__(256) __nv_bfloat16 g_Bt[(size_t)2 * NSIG * KDIM];
__device__ float g_mean[KDIM];
__device__ unsigned long long g_best[M_OUT];

// ---------------- helpers ----------------
__device__ __forceinline__ uint32_t smem_u32(const void* p) {
    uint32_t a;
    asm("{ .reg .u64 t; cvta.to.shared.u64 t, %1; cvt.u32.u64 %0, t; }" : "=r"(a) : "l"(p));
    return a;
}
__device__ __forceinline__ void cpa16(uint32_t s, const void* g) {
    asm volatile("cp.async.cg.shared.global [%0], [%1], 16;" :: "r"(s), "l"(g) : "memory");
}
__device__ __forceinline__ uint32_t lds32(uint32_t a) {
    uint32_t v;
    asm("ld.shared.b32 %0, [%1];" : "=r"(v) : "r"(a));
    return v;
}
__device__ __forceinline__ void mma_bf16(float* c, uint32_t a0, uint32_t a1,
                                         uint32_t a2, uint32_t a3,
                                         uint32_t b0, uint32_t b1) {
    asm volatile(
        "mma.sync.aligned.m16n8k16.row.col.f32.bf16.bf16.f32 "
        "{%0,%1,%2,%3}, {%4,%5,%6,%7}, {%8,%9}, {%0,%1,%2,%3};"
        : "+f"(c[0]), "+f"(c[1]), "+f"(c[2]), "+f"(c[3])
        : "r"(a0), "r"(a1), "r"(a2), "r"(a3), "r"(b0), "r"(b1));
}

// ---------------- kernel 1: per-row means ----------------
__global__ void mean_kernel(const float* __restrict__ x) {
    __shared__ float red[256];
    const int n = blockIdx.x;
    const float4* row = (const float4*)(x + (size_t)n * NSIG);
    float s = 0.f;
#pragma unroll
    for (int c = 0; c < 4; ++c) {
        float4 v = row[threadIdx.x + c * 256];
        s += (v.x + v.y) + (v.z + v.w);
    }
    red[threadIdx.x] = s;
    __syncthreads();
    for (int off = 128; off > 0; off >>= 1) {
        if (threadIdx.x < off) red[threadIdx.x] += red[threadIdx.x + off];
        __syncthreads();
    }
    if (threadIdx.x == 0) g_mean[n] = red[0] * (1.0f / 4096.0f);
}

// ---------------- kernel 2: trig table -> 4 bf16 split planes ----------------
__global__ void trig_kernel() {
    const long long idx = (long long)blockIdx.x * blockDim.x + threadIdx.x;
    if (idx >= (long long)MPAD * KDIM) return;
    const int i = (int)(idx >> 12);
    const int n = (int)(idx & 4095);
    float c = 0.f, s = 0.f;
    if (i < M_OUT) {
        const float t = (float)(i * n);
        const float a = CANG * t;
        const float kf = rintf(a * 0.63661977236758134f);
        const int   k  = (int)kf;
        float r = fmaf(kf, -1.57079601287841796875f, a);
        r       = fmaf(kf, -3.1391647326017916e-07f, r);
        r       = fmaf(kf, -5.3903025299577648e-15f, r);
        const float z = r * r;
        const float sinp = r * fmaf(z, fmaf(z, fmaf(z, -1.9515295891e-4f,
                                                8.3321608736e-3f),
                                        -1.6666654611e-1f), 1.0f);
        const float cosp = fmaf(z, fmaf(z, fmaf(z, fmaf(z, 2.443315711809948e-5f,
                                                    -1.388731625493765e-3f),
                                            4.166664568298827e-2f),
                                    -0.5f), 1.0f);
        const int q = k & 3;
        if (q == 0)      { c =  cosp; s =  sinp; }
        else if (q == 1) { c = -sinp; s =  cosp; }
        else if (q == 2) { c = -cosp; s = -sinp; }
        else             { c =  sinp; s = -cosp; }
    }
    float v = c;
#pragma unroll
    for (int part = 0; part < 2; ++part) {
        const __nv_bfloat16 b0 = __float2bfloat16_rn(v);
        const float r1 = v - __bfloat162float(b0);
        const __nv_bfloat16 b1 = __float2bfloat16_rn(r1);
        const size_t base = ((size_t)(part * 2) * MPAD + i) * KDIM + n;
        g_At[base]                       = b0;
        g_At[base + (size_t)MPAD * KDIM] = b1;
        v = s;
    }
    if (idx < M_OUT) g_best[idx] = 0ull;
}

// ---------------- kernel 3: transpose + demean + 2-way split B ----------------
__global__ void bsplit_kernel(const float* __restrict__ x) {
    __shared__ float tile[32][33];
    const int k0 = blockIdx.x * 32;
    const int n0 = blockIdx.y * 32;
    const int tx = threadIdx.x, ty = threadIdx.y;   // 32 x 8
#pragma unroll
    for (int r = 0; r < 4; ++r) {
        const int k = ty + r * 8;
        tile[k][tx] = x[(size_t)(k0 + k) * NSIG + n0 + tx] - g_mean[k0 + k];
    }
    __syncthreads();
#pragma unroll
    for (int r = 0; r < 4; ++r) {
        const int n = ty + r * 8;
        const float v = tile[tx][n];
        const __nv_bfloat16 b0 = __float2bfloat16_rn(v);
        const float r1 = v - __bfloat162float(b0);
        const __nv_bfloat16 b1 = __float2bfloat16_rn(r1);
        const size_t base = ((size_t)(n0 + n)) * KDIM + k0 + tx;
        g_Bt[base]                       = b0;
        g_Bt[base + (size_t)NSIG * KDIM] = b1;
    }
}

// ---------------- kernel 4: bf16x3 HMMA dual GEMM + fused argmax ----------------
// smem per stage: A: 2 planes x 128 rows x 80B = 20480; B: 2 x 64 x 80B = 10240
#define SM_STAGE 30720
#define SM_APL   10240
#define SM_BOFF  20480
#define SM_BPL   5120
#define SM_TOTAL (2 * SM_STAGE)

__global__ __launch_bounds__(256, 2) void gemm_mma_kernel() {
    extern __shared__ char smem[];
    const uint32_t sb = smem_u32(smem);
    const int tid = threadIdx.x;
    const int warp = tid >> 5;
    const int lane = tid & 31;
    const int gr = lane >> 2;          // 0..7
    const int tig = lane & 3;          // 0..3
    const int wm = warp >> 1;          // 0..3 -> M' rows 32*wm
    const int wn = warp & 1;           // 0..1 -> N cols 32*wn
    const int i0 = blockIdx.y * 64;
    const int j0 = blockIdx.x * 64;

    // loader mapping (per thread): A 4 units, B 2 units (16B each)
    const int lr  = tid >> 2;          // 0..63 row
    const int seg = tid & 3;           // 16B segment
    const __nv_bfloat16* gA[4];
    uint32_t sA[4];
#pragma unroll
    for (int p = 0; p < 4; ++p) {
        // gmem plane p = part*2 + split; smem plane = split (p&1), row block = part (p>>1)
        gA[p] = g_At + ((size_t)p * MPAD + i0 + lr) * KDIM + seg * 8;
        sA[p] = sb + (p & 1) * SM_APL + (((p >> 1) * 64) + lr) * 80 + seg * 16;
    }
    const __nv_bfloat16* gB[2];
    uint32_t sB[2];
#pragma unroll
    for (int p = 0; p < 2; ++p) {
        gB[p] = g_Bt + ((size_t)p * NSIG + j0 + lr) * KDIM + seg * 8;
        sB[p] = sb + SM_BOFF + p * SM_BPL + lr * 80 + seg * 16;
    }

    float acc[2][4][4];
#pragma unroll
    for (int mt = 0; mt < 2; ++mt)
#pragma unroll
        for (int nt = 0; nt < 4; ++nt)
#pragma unroll
            for (int e = 0; e < 4; ++e) acc[mt][nt][e] = 0.f;

    // prologue: stage 0 = k-tile 0
    {
#pragma unroll
        for (int p = 0; p < 4; ++p) cpa16(sA[p], gA[p]);
#pragma unroll
        for (int p = 0; p < 2; ++p) cpa16(sB[p], gB[p]);
        asm volatile("cp.async.commit_group;" ::: "memory");
    }

    const uint32_t aW = sb + (32 * wm + gr) * 80 + tig * 4;
    const uint32_t bW = sb + SM_BOFF + (32 * wn + gr) * 80 + tig * 4;

    for (int kt = 0; kt < KDIM / 32; ++kt) {
        if (kt + 1 < KDIM / 32) {
            const int ke = (kt + 1) * 32;
            const uint32_t so = ((kt + 1) & 1) * SM_STAGE;
#pragma unroll
            for (int p = 0; p < 4; ++p) cpa16(sA[p] + so, gA[p] + ke);
#pragma unroll
            for (int p = 0; p < 2; ++p) cpa16(sB[p] + so, gB[p] + ke);
            asm volatile("cp.async.commit_group;" ::: "memory");
            asm volatile("cp.async.wait_group 1;" ::: "memory");
        } else {
            asm volatile("cp.async.wait_group 0;" ::: "memory");
        }
        __syncthreads();

        const uint32_t so = (kt & 1) * SM_STAGE;
#pragma unroll
        for (int ks = 0; ks < 2; ++ks) {
            const uint32_t kb = ks * 32;
            // B fragments: 2 planes x 4 n-tiles x 2 regs
            uint32_t bf[2][4][2];
#pragma unroll
            for (int q = 0; q < 2; ++q)
#pragma unroll
                for (int nt = 0; nt < 4; ++nt) {
                    const uint32_t a = bW + so + q * SM_BPL + nt * (8 * 80) + kb;
                    bf[q][nt][0] = lds32(a);
                    bf[q][nt][1] = lds32(a + 16);
                }
            // 3-term split: A-split0 x {B0, B1}; A-split1 x {B0}
#pragma unroll
            for (int p = 0; p < 2; ++p) {
#pragma unroll
                for (int mt = 0; mt < 2; ++mt) {
                    const uint32_t a = aW + so + p * SM_APL + mt * (16 * 80) + kb;
                    const uint32_t a0 = lds32(a);
                    const uint32_t a1 = lds32(a + 8 * 80);
                    const uint32_t a2 = lds32(a + 16);
                    const uint32_t a3 = lds32(a + 8 * 80 + 16);
                    const int nq = (p == 0) ? 2 : 1;
#pragma unroll
                    for (int q = 0; q < 2; ++q) {
                        if (q < nq) {
#pragma unroll
                            for (int nt = 0; nt < 4; ++nt)
                                mma_bf16(acc[mt][nt], a0, a1, a2, a3,
                                         bf[q][nt][0], bf[q][nt][1]);
                        }
                    }
                }
            }
        }
        __syncthreads();
    }

    // ---- epilogue: smem reused as D[128][66] f32 + sbest ----
    float* Dsm = (float*)smem;
    unsigned long long* sbest = (unsigned long long*)(smem + 128 * 66 * 4);
#pragma unroll
    for (int mt = 0; mt < 2; ++mt)
#pragma unroll
        for (int nt = 0; nt < 4; ++nt) {
            const int m = 32 * wm + 16 * mt;
            const int n = 32 * wn + 8 * nt + 2 * tig;
            *(float2*)(&Dsm[(m + gr) * 66 + n])     = make_float2(acc[mt][nt][0], acc[mt][nt][1]);
            *(float2*)(&Dsm[(m + gr + 8) * 66 + n]) = make_float2(acc[mt][nt][2], acc[mt][nt][3]);
        }
    if (tid < 64) sbest[tid] = 0ull;
    __syncthreads();

    {
        const int r = tid & 63;
        const int c0 = (tid >> 6) * 16;
        float best = -1.0f;
        unsigned bj = 0;
#pragma unroll
        for (int c = 0; c < 16; ++c) {
            const int col = c0 + c;
            const float re = Dsm[r * 66 + col];
            const float im = Dsm[(64 + r) * 66 + col];
            const float v = fmaf(re, re, im * im);
            const unsigned j = (unsigned)(j0 + col);
            if (v > best) { best = v; bj = j; }
        }
        const unsigned long long p =
            ((unsigned long long)__float_as_uint(best) << 32) |
            (unsigned long long)(0xFFFFFFFFu - bj);
        atomicMax(&sbest[r], p);
    }
    __syncthreads();
    if (tid < 64) {
        const int gi = i0 + tid;
        if (gi < M_OUT) atomicMax(&g_best[gi], sbest[tid]);
    }
}

// ---------------- kernel 5: map argmax index -> heart rate ----------------
__global__ void final_kernel(float* __restrict__ out) {
    const int i = blockIdx.x * blockDim.x + threadIdx.x;
    if (i < M_OUT) {
        const unsigned j = 0xFFFFFFFFu - (unsigned)(g_best[i] & 0xFFFFFFFFull);
        const float freq = (float)j / DEN;
        out[i] = freq * 60.0f;
    }
}

extern "C" void kernel_launch(void* const* d_in, const int* in_sizes, int n_in,
                              void* d_out, int out_size) {
    const float* x = (const float*)d_in[0];
    float* out = (float*)d_out;

    cudaFuncSetAttribute(gemm_mma_kernel,
                         cudaFuncAttributeMaxDynamicSharedMemorySize, SM_TOTAL);

    mean_kernel<<<KDIM, 256>>>(x);

    const long long trig_total = (long long)MPAD * KDIM;
    trig_kernel<<<(unsigned)((trig_total + 255) / 256), 256>>>();

    bsplit_kernel<<<dim3(KDIM / 32, NSIG / 32), dim3(32, 8)>>>(x);

    gemm_mma_kernel<<<dim3(NSIG / 64, MPAD / 64), 256, SM_TOTAL>>>();

    final_kernel<<<(M_OUT + 255) / 256, 256>>>(out);
}

// round 11
// speedup vs baseline: 2.8819x; 1.0965x over previous
#include <cuda_runtime.h>
#include <cuda_bf16.h>
#include <cstdint>

#define M_OUT 2049
#define MPAD  2112          // 33 * 64
#define NSIG  4096
#define KDIM  4096

static constexpr float CANG = (float)(-2.0 * 3.14 / 4096.0);
static constexpr float DEN  = (float)(4096.0 / 30.0);

// A planes: pidx = part*2 + split (part 0=cos 1=sin), [pidx][row][k] bf16
__device__ __align__(256) __nv_bfloat16 g_At[(size_t)4 * MPAD * KDIM];
// B planes: [split][n][k] bf16 (x transposed, demeaned, 2-way split)
__device__ __align__(256) __nv_bfloat16 g_Bt[(size_t)2 * NSIG * KDIM];
__device__ float g_mean[KDIM];
__device__ unsigned long long g_best[M_OUT];

// ---------------- helpers ----------------
__device__ __forceinline__ uint32_t smem_u32(const void* p) {
    uint32_t a;
    asm("{ .reg .u64 t; cvta.to.shared.u64 t, %1; cvt.u32.u64 %0, t; }" : "=r"(a) : "l"(p));
    return a;
}
__device__ __forceinline__ void cpa16(uint32_t s, const void* g) {
    asm volatile("cp.async.cg.shared.global [%0], [%1], 16;" :: "r"(s), "l"(g) : "memory");
}
__device__ __forceinline__ void ldsm_x4(uint32_t& r0, uint32_t& r1,
                                        uint32_t& r2, uint32_t& r3, uint32_t addr) {
    asm volatile("ldmatrix.sync.aligned.m8n8.x4.shared.b16 {%0,%1,%2,%3}, [%4];"
                 : "=r"(r0), "=r"(r1), "=r"(r2), "=r"(r3) : "r"(addr));
}
__device__ __forceinline__ void mma_bf16(float* c, uint32_t a0, uint32_t a1,
                                         uint32_t a2, uint32_t a3,
                                         uint32_t b0, uint32_t b1) {
    asm volatile(
        "mma.sync.aligned.m16n8k16.row.col.f32.bf16.bf16.f32 "
        "{%0,%1,%2,%3}, {%4,%5,%6,%7}, {%8,%9}, {%0,%1,%2,%3};"
        : "+f"(c[0]), "+f"(c[1]), "+f"(c[2]), "+f"(c[3])
        : "r"(a0), "r"(a1), "r"(a2), "r"(a3), "r"(b0), "r"(b1));
}

// ---------------- kernel 1: per-row means ----------------
__global__ void mean_kernel(const float* __restrict__ x) {
    __shared__ float red[256];
    const int n = blockIdx.x;
    const float4* row = (const float4*)(x + (size_t)n * NSIG);
    float s = 0.f;
#pragma unroll
    for (int c = 0; c < 4; ++c) {
        float4 v = row[threadIdx.x + c * 256];
        s += (v.x + v.y) + (v.z + v.w);
    }
    red[threadIdx.x] = s;
    __syncthreads();
    for (int off = 128; off > 0; off >>= 1) {
        if (threadIdx.x < off) red[threadIdx.x] += red[threadIdx.x + off];
        __syncthreads();
    }
    if (threadIdx.x == 0) g_mean[n] = red[0] * (1.0f / 4096.0f);
}

// ---------------- kernel 2: trig table -> 4 bf16 split planes ----------------
__global__ void trig_kernel() {
    const long long idx = (long long)blockIdx.x * blockDim.x + threadIdx.x;
    if (idx >= (long long)MPAD * KDIM) return;
    const int i = (int)(idx >> 12);
    const int n = (int)(idx & 4095);
    float c = 0.f, s = 0.f;
    if (i < M_OUT) {
        const float t = (float)(i * n);
        const float a = CANG * t;
        const float kf = rintf(a * 0.63661977236758134f);
        const int   k  = (int)kf;
        float r = fmaf(kf, -1.57079601287841796875f, a);
        r       = fmaf(kf, -3.1391647326017916e-07f, r);
        r       = fmaf(kf, -5.3903025299577648e-15f, r);
        const float z = r * r;
        const float sinp = r * fmaf(z, fmaf(z, fmaf(z, -1.9515295891e-4f,
                                                8.3321608736e-3f),
                                        -1.6666654611e-1f), 1.0f);
        const float cosp = fmaf(z, fmaf(z, fmaf(z, fmaf(z, 2.443315711809948e-5f,
                                                    -1.388731625493765e-3f),
                                            4.166664568298827e-2f),
                                    -0.5f), 1.0f);
        const int q = k & 3;
        if (q == 0)      { c =  cosp; s =  sinp; }
        else if (q == 1) { c = -sinp; s =  cosp; }
        else if (q == 2) { c = -cosp; s = -sinp; }
        else             { c =  sinp; s = -cosp; }
    }
    float v = c;
#pragma unroll
    for (int part = 0; part < 2; ++part) {
        const __nv_bfloat16 b0 = __float2bfloat16_rn(v);
        const float r1 = v - __bfloat162float(b0);
        const __nv_bfloat16 b1 = __float2bfloat16_rn(r1);
        const size_t base = ((size_t)(part * 2) * MPAD + i) * KDIM + n;
        g_At[base]                       = b0;
        g_At[base + (size_t)MPAD * KDIM] = b1;
        v = s;
    }
    if (idx < M_OUT) g_best[idx] = 0ull;
}

// ---------------- kernel 3: transpose + demean + 2-way split B ----------------
__global__ void bsplit_kernel(const float* __restrict__ x) {
    __shared__ float tile[32][33];
    const int k0 = blockIdx.x * 32;
    const int n0 = blockIdx.y * 32;
    const int tx = threadIdx.x, ty = threadIdx.y;   // 32 x 8
#pragma unroll
    for (int r = 0; r < 4; ++r) {
        const int k = ty + r * 8;
        tile[k][tx] = x[(size_t)(k0 + k) * NSIG + n0 + tx] - g_mean[k0 + k];
    }
    __syncthreads();
#pragma unroll
    for (int r = 0; r < 4; ++r) {
        const int n = ty + r * 8;
        const float v = tile[tx][n];
        const __nv_bfloat16 b0 = __float2bfloat16_rn(v);
        const float r1 = v - __bfloat162float(b0);
        const __nv_bfloat16 b1 = __float2bfloat16_rn(r1);
        const size_t base = ((size_t)(n0 + n)) * KDIM + k0 + tx;
        g_Bt[base]                       = b0;
        g_Bt[base + (size_t)NSIG * KDIM] = b1;
    }
}

// ---------------- kernel 4: bf16x3 HMMA dual GEMM (ldmatrix feed) + argmax ----------------
// smem per stage: A: 2 planes x 128 rows x 80B = 20480; B: 2 x 64 x 80B = 10240
#define SM_STAGE 30720
#define SM_APL   10240
#define SM_BOFF  20480
#define SM_BPL   5120
#define SM_TOTAL (2 * SM_STAGE)

__global__ __launch_bounds__(256, 2) void gemm_mma_kernel() {
    extern __shared__ char smem[];
    const uint32_t sb = smem_u32(smem);
    const int tid = threadIdx.x;
    const int warp = tid >> 5;
    const int lane = tid & 31;
    const int gr = lane >> 2;          // 0..7 (epilogue row)
    const int tig = lane & 3;          // 0..3
    const int wm = warp >> 1;          // 0..3 -> M' rows 32*wm
    const int wn = warp & 1;           // 0..1 -> N cols 32*wn
    const int i0 = blockIdx.y * 64;
    const int j0 = blockIdx.x * 64;

    // loader mapping (per thread): A 4 units, B 2 units (16B each)
    const int lr  = tid >> 2;          // 0..63 row
    const int seg = tid & 3;           // 16B segment
    const __nv_bfloat16* gA[4];
    uint32_t sA[4];
#pragma unroll
    for (int p = 0; p < 4; ++p) {
        gA[p] = g_At + ((size_t)p * MPAD + i0 + lr) * KDIM + seg * 8;
        sA[p] = sb + (p & 1) * SM_APL + (((p >> 1) * 64) + lr) * 80 + seg * 16;
    }
    const __nv_bfloat16* gB[2];
    uint32_t sB[2];
#pragma unroll
    for (int p = 0; p < 2; ++p) {
        gB[p] = g_Bt + ((size_t)p * NSIG + j0 + lr) * KDIM + seg * 8;
        sB[p] = sb + SM_BOFF + p * SM_BPL + lr * 80 + seg * 16;
    }

    float acc[2][4][4];
#pragma unroll
    for (int mt = 0; mt < 2; ++mt)
#pragma unroll
        for (int nt = 0; nt < 4; ++nt)
#pragma unroll
            for (int e = 0; e < 4; ++e) acc[mt][nt][e] = 0.f;

    // prologue: stage 0 = k-tile 0
    {
#pragma unroll
        for (int p = 0; p < 4; ++p) cpa16(sA[p], gA[p]);
#pragma unroll
        for (int p = 0; p < 2; ++p) cpa16(sB[p], gB[p]);
        asm volatile("cp.async.commit_group;" ::: "memory");
    }

    // ldmatrix lane addressing: m = lane>>3 selects the 8x8 submatrix
    const int lm = lane >> 3;          // 0..3
    const int lrow = lane & 7;         // row within submatrix
    // A: m0=(r0,k0) m1=(r+8,k0) m2=(r0,k+8) m3=(r+8,k+8)
    const uint32_t aLane = (uint32_t)(((lm & 1) * 8 + lrow) * 80 + (lm >> 1) * 16);
    // B: m0=(nt,k0) m1=(nt,k+8) m2=(nt+1,k0) m3=(nt+1,k+8)
    const uint32_t bLane = (uint32_t)(((lm >> 1) * 8 + lrow) * 80 + (lm & 1) * 16);
    const uint32_t aBase = sb + (uint32_t)(32 * wm) * 80 + aLane;
    const uint32_t bBase = sb + SM_BOFF + (uint32_t)(32 * wn) * 80 + bLane;

    for (int kt = 0; kt < KDIM / 32; ++kt) {
        if (kt + 1 < KDIM / 32) {
            const int ke = (kt + 1) * 32;
            const uint32_t so = ((kt + 1) & 1) * SM_STAGE;
#pragma unroll
            for (int p = 0; p < 4; ++p) cpa16(sA[p] + so, gA[p] + ke);
#pragma unroll
            for (int p = 0; p < 2; ++p) cpa16(sB[p] + so, gB[p] + ke);
            asm volatile("cp.async.commit_group;" ::: "memory");
            asm volatile("cp.async.wait_group 1;" ::: "memory");
        } else {
            asm volatile("cp.async.wait_group 0;" ::: "memory");
        }
        __syncthreads();

        const uint32_t so = (kt & 1) * SM_STAGE;
#pragma unroll
        for (int ks = 0; ks < 2; ++ks) {
            const uint32_t kb = ks * 32;
            // B fragments: 2 planes x 4 n-tiles x 2 regs (one ldsm.x4 per plane per tile-pair)
            uint32_t bf[2][4][2];
#pragma unroll
            for (int q = 0; q < 2; ++q)
#pragma unroll
                for (int ntp = 0; ntp < 2; ++ntp) {
                    const uint32_t a = bBase + so + q * SM_BPL + ntp * (16 * 80) + kb;
                    ldsm_x4(bf[q][ntp * 2][0], bf[q][ntp * 2][1],
                            bf[q][ntp * 2 + 1][0], bf[q][ntp * 2 + 1][1], a);
                }
            // 3-term split: A-split0 x {B0, B1}; A-split1 x {B0}
#pragma unroll
            for (int p = 0; p < 2; ++p) {
#pragma unroll
                for (int mt = 0; mt < 2; ++mt) {
                    const uint32_t a = aBase + so + p * SM_APL + mt * (16 * 80) + kb;
                    uint32_t a0, a1, a2, a3;
                    ldsm_x4(a0, a1, a2, a3, a);
                    const int nq = (p == 0) ? 2 : 1;
#pragma unroll
                    for (int q = 0; q < 2; ++q) {
                        if (q < nq) {
#pragma unroll
                            for (int nt = 0; nt < 4; ++nt)
                                mma_bf16(acc[mt][nt], a0, a1, a2, a3,
                                         bf[q][nt][0], bf[q][nt][1]);
                        }
                    }
                }
            }
        }
        __syncthreads();
    }

    // ---- epilogue: smem reused as D[128][66] f32 + sbest ----
    float* Dsm = (float*)smem;
    unsigned long long* sbest = (unsigned long long*)(smem + 128 * 66 * 4);
#pragma unroll
    for (int mt = 0; mt < 2; ++mt)
#pragma unroll
        for (int nt = 0; nt < 4; ++nt) {
            const int m = 32 * wm + 16 * mt;
            const int n = 32 * wn + 8 * nt + 2 * tig;
            *(float2*)(&Dsm[(m + gr) * 66 + n])     = make_float2(acc[mt][nt][0], acc[mt][nt][1]);
            *(float2*)(&Dsm[(m + gr + 8) * 66 + n]) = make_float2(acc[mt][nt][2], acc[mt][nt][3]);
        }
    if (tid < 64) sbest[tid] = 0ull;
    __syncthreads();

    {
        const int r = tid & 63;
        const int c0 = (tid >> 6) * 16;
        float best = -1.0f;
        unsigned bj = 0;
#pragma unroll
        for (int c = 0; c < 16; ++c) {
            const int col = c0 + c;
            const float re = Dsm[r * 66 + col];
            const float im = Dsm[(64 + r) * 66 + col];
            const float v = fmaf(re, re, im * im);
            const unsigned j = (unsigned)(j0 + col);
            if (v > best) { best = v; bj = j; }
        }
        const unsigned long long p =
            ((unsigned long long)__float_as_uint(best) << 32) |
            (unsigned long long)(0xFFFFFFFFu - bj);
        atomicMax(&sbest[r], p);
    }
    __syncthreads();
    if (tid < 64) {
        const int gi = i0 + tid;
        if (gi < M_OUT) atomicMax(&g_best[gi], sbest[tid]);
    }
}

// ---------------- kernel 5: map argmax index -> heart rate ----------------
__global__ void final_kernel(float* __restrict__ out) {
    const int i = blockIdx.x * blockDim.x + threadIdx.x;
    if (i < M_OUT) {
        const unsigned j = 0xFFFFFFFFu - (unsigned)(g_best[i] & 0xFFFFFFFFull);
        const float freq = (float)j / DEN;
        out[i] = freq * 60.0f;
    }
}

extern "C" void kernel_launch(void* const* d_in, const int* in_sizes, int n_in,
                              void* d_out, int out_size) {
    const float* x = (const float*)d_in[0];
    float* out = (float*)d_out;

    cudaFuncSetAttribute(gemm_mma_kernel,
                         cudaFuncAttributeMaxDynamicSharedMemorySize, SM_TOTAL);

    mean_kernel<<<KDIM, 256>>>(x);

    const long long trig_total = (long long)MPAD * KDIM;
    trig_kernel<<<(unsigned)((trig_total + 255) / 256), 256>>>();

    bsplit_kernel<<<dim3(KDIM / 32, NSIG / 32), dim3(32, 8)>>>(x);

    gemm_mma_kernel<<<dim3(NSIG / 64, MPAD / 64), 256, SM_TOTAL>>>();

    final_kernel<<<(M_OUT + 255) / 256, 256>>>(out);
}